// round 1
// baseline (speedup 1.0000x reference)
#include <cuda_runtime.h>
#include <cuda_bf16.h>
#include <math.h>

// ---------------- problem constants ----------------
#define B_TOT   2048          // B * nW
#define NW      64            // windows per batch elem
#define BB      32            // batch
#define NWIN    49            // window tokens
#define PLEN    20            // prompt tokens
#define NTOK    69            // PLEN + NWIN
#define CDIM    128
#define HEADS   4
#define DH      32
#define QK_SCALE 0.17677669529663687f   // 32^-0.5
#define NROWS   (B_TOT*NTOK)  // 141312, divisible by 64

// ---------------- scratch (static device memory; allocation-free) ----------------
__device__ float g_q [B_TOT*HEADS*NTOK*DH];   // 18,087,936 floats
__device__ float g_k [B_TOT*HEADS*NTOK*DH];
__device__ float g_v [B_TOT*HEADS*NTOK*DH];
__device__ float g_ao[B_TOT*NTOK*CDIM];       // attention output, [B_, N, C]
__device__ float g_pp[B_TOT*PLEN*CDIM];       // proj output of prompt rows

// ============================================================================
// Kernel 1: qkv = concat(prompts, x) @ W_qkv + b_qkv, scatter into q/k/v
// grid (2208, 3), block 256. Tile: 64 rows x 128 cols, K tiled by 32.
// ============================================================================
__global__ void qkv_kernel(const float* __restrict__ x,
                           const float* __restrict__ pr,
                           const float* __restrict__ W,
                           const float* __restrict__ bias)
{
    __shared__ float a_s[64][33];
    __shared__ float b_s[32][128];

    const int row0 = blockIdx.x * 64;
    const int col0 = blockIdx.y * 128;   // which = blockIdx.y (0=q,1=k,2=v)
    const int tid  = threadIdx.x;
    const int ty   = tid >> 4;           // 0..15
    const int tx   = tid & 15;           // 0..15

    float acc[4][8];
    #pragma unroll
    for (int i = 0; i < 4; i++)
        #pragma unroll
        for (int j = 0; j < 8; j++) acc[i][j] = 0.f;

    for (int k0 = 0; k0 < 128; k0 += 32) {
        // A tile: 64x32 (concat gather)
        #pragma unroll
        for (int i = tid; i < 64*32; i += 256) {
            int r  = i >> 5;
            int kk = i & 31;
            int grow = row0 + r;
            int b_ = grow / NTOK;
            int n  = grow % NTOK;
            int k  = k0 + kk;
            float val;
            if (n < PLEN) val = pr[((b_ / NW)*PLEN + n)*CDIM + k];
            else          val = x[((long)b_*NWIN + (n - PLEN))*CDIM + k];
            a_s[r][kk] = val;
        }
        // B tile: 32x128 of W_qkv [128,384]
        #pragma unroll
        for (int i = tid; i < 32*128; i += 256) {
            int kk = i >> 7;
            int c  = i & 127;
            b_s[kk][c] = W[(k0 + kk)*384 + col0 + c];
        }
        __syncthreads();

        #pragma unroll
        for (int kk = 0; kk < 32; kk++) {
            float a[4];
            #pragma unroll
            for (int i = 0; i < 4; i++) a[i] = a_s[ty*4 + i][kk];
            float4 b0 = *reinterpret_cast<const float4*>(&b_s[kk][tx*8]);
            float4 b1 = *reinterpret_cast<const float4*>(&b_s[kk][tx*8 + 4]);
            float b[8] = {b0.x, b0.y, b0.z, b0.w, b1.x, b1.y, b1.z, b1.w};
            #pragma unroll
            for (int i = 0; i < 4; i++)
                #pragma unroll
                for (int j = 0; j < 8; j++)
                    acc[i][j] = fmaf(a[i], b[j], acc[i][j]);
        }
        __syncthreads();
    }

    // scatter to q/k/v with layout [B_, H, N, DH]
    float* dst = (blockIdx.y == 0) ? g_q : (blockIdx.y == 1) ? g_k : g_v;
    #pragma unroll
    for (int i = 0; i < 4; i++) {
        int grow = row0 + ty*4 + i;
        int b_ = grow / NTOK;
        int n  = grow % NTOK;
        #pragma unroll
        for (int j = 0; j < 8; j++) {
            int c      = col0 + tx*8 + j;   // global col in [0,384)
            int within = c & 127;
            int h      = within >> 5;
            int d      = within & 31;
            float v = acc[i][j] + bias[c];
            dst[(((long)b_*HEADS + h)*NTOK + n)*DH + d] = v;
        }
    }
}

// ============================================================================
// Kernel 2: attention per (b_, h). grid 8192, block 256.
// scores -> export raw slice -> scale + bias + mask -> softmax -> attn@v
// ============================================================================
__global__ void attn_kernel(const float* __restrict__ table,
                            const float* __restrict__ mask,
                            float* __restrict__ out_attnw)
{
    __shared__ float q_s[NTOK][DH+1];
    __shared__ float k_s[NTOK][DH+1];
    __shared__ float v_s[NTOK][DH+1];
    __shared__ float s_s[NTOK][NTOK+3];   // 69 x 72

    const int bh = blockIdx.x;            // 0..8191
    const int b_ = bh >> 2;
    const int h  = bh & 3;
    const int tid = threadIdx.x;

    const float* qp = g_q + (long)bh * NTOK * DH;
    const float* kp = g_k + (long)bh * NTOK * DH;
    const float* vp = g_v + (long)bh * NTOK * DH;

    for (int i = tid; i < NTOK*DH; i += 256) {
        int n = i / DH, d = i % DH;
        q_s[n][d] = qp[i];
        k_s[n][d] = kp[i];
        v_s[n][d] = vp[i];
    }
    __syncthreads();

    const int w = b_ & (NW - 1);
    const float* mrow = mask + (long)w * NWIN * NWIN;

    for (int idx = tid; idx < NTOK*NTOK; idx += 256) {
        int n = idx / NTOK, m = idx % NTOK;
        float s = 0.f;
        #pragma unroll
        for (int d = 0; d < DH; d++) s = fmaf(q_s[n][d], k_s[m][d], s);
        if (n < PLEN && m >= PLEN)    // raw pre-scale q.k export
            out_attnw[((long)bh*PLEN + n)*NWIN + (m - PLEN)] = s;
        s *= QK_SCALE;
        if (n >= PLEN && m >= PLEN) {
            int i = n - PLEN, j = m - PLEN;
            int dr = (i/7) - (j/7) + 6;
            int dc = (i%7) - (j%7) + 6;
            s += table[(dr*13 + dc)*HEADS + h] + mrow[i*NWIN + j];
        }
        s_s[n][m] = s;
    }
    __syncthreads();

    // softmax: one warp per row
    const int warp = tid >> 5, lane = tid & 31;
    for (int n = warp; n < NTOK; n += 8) {
        float mx = -INFINITY;
        for (int m = lane; m < NTOK; m += 32) mx = fmaxf(mx, s_s[n][m]);
        #pragma unroll
        for (int o = 16; o > 0; o >>= 1) mx = fmaxf(mx, __shfl_xor_sync(0xffffffffu, mx, o));
        float sum = 0.f;
        for (int m = lane; m < NTOK; m += 32) {
            float e = __expf(s_s[n][m] - mx);
            s_s[n][m] = e;
            sum += e;
        }
        #pragma unroll
        for (int o = 16; o > 0; o >>= 1) sum += __shfl_xor_sync(0xffffffffu, sum, o);
        float inv = 1.0f / sum;
        for (int m = lane; m < NTOK; m += 32) s_s[n][m] *= inv;
    }
    __syncthreads();

    // out = attn @ v, written as [B_, N, C] with C index = h*32 + d
    float* ao = g_ao + (long)b_*NTOK*CDIM + h*DH;
    for (int idx = tid; idx < NTOK*DH; idx += 256) {
        int n = idx / DH, d = idx % DH;
        float acc = 0.f;
        #pragma unroll 4
        for (int m = 0; m < NTOK; m++) acc = fmaf(s_s[n][m], v_s[m][d], acc);
        ao[n*CDIM + d] = acc;
    }
}

// ============================================================================
// Kernel 3: proj GEMM. grid 2208, block 256. Window rows -> d_out, prompt
// rows -> g_pp.
// ============================================================================
__global__ void proj_kernel(const float* __restrict__ W,
                            const float* __restrict__ bias,
                            float* __restrict__ xout)
{
    __shared__ float a_s[64][33];
    __shared__ float b_s[32][128];

    const int row0 = blockIdx.x * 64;
    const int tid  = threadIdx.x;
    const int ty   = tid >> 4;
    const int tx   = tid & 15;

    float acc[4][8];
    #pragma unroll
    for (int i = 0; i < 4; i++)
        #pragma unroll
        for (int j = 0; j < 8; j++) acc[i][j] = 0.f;

    for (int k0 = 0; k0 < 128; k0 += 32) {
        #pragma unroll
        for (int i = tid; i < 64*32; i += 256) {
            int r = i >> 5, kk = i & 31;
            a_s[r][kk] = g_ao[((long)(row0 + r))*CDIM + k0 + kk];
        }
        #pragma unroll
        for (int i = tid; i < 32*128; i += 256) {
            int kk = i >> 7, c = i & 127;
            b_s[kk][c] = W[(k0 + kk)*CDIM + c];
        }
        __syncthreads();

        #pragma unroll
        for (int kk = 0; kk < 32; kk++) {
            float a[4];
            #pragma unroll
            for (int i = 0; i < 4; i++) a[i] = a_s[ty*4 + i][kk];
            float4 b0 = *reinterpret_cast<const float4*>(&b_s[kk][tx*8]);
            float4 b1 = *reinterpret_cast<const float4*>(&b_s[kk][tx*8 + 4]);
            float b[8] = {b0.x, b0.y, b0.z, b0.w, b1.x, b1.y, b1.z, b1.w};
            #pragma unroll
            for (int i = 0; i < 4; i++)
                #pragma unroll
                for (int j = 0; j < 8; j++)
                    acc[i][j] = fmaf(a[i], b[j], acc[i][j]);
        }
        __syncthreads();
    }

    #pragma unroll
    for (int i = 0; i < 4; i++) {
        int grow = row0 + ty*4 + i;
        int b_ = grow / NTOK;
        int n  = grow % NTOK;
        #pragma unroll
        for (int j = 0; j < 8; j++) {
            int c = tx*8 + j;
            float v = acc[i][j] + bias[c];
            if (n >= PLEN) xout[((long)b_*NWIN + (n - PLEN))*CDIM + c] = v;
            else           g_pp[((long)b_*PLEN + n)*CDIM + c] = v;
        }
    }
}

// ============================================================================
// Kernel 4: prompts_out[b,p,c] = mean over 64 windows of g_pp
// ============================================================================
__global__ void pmean_kernel(float* __restrict__ pout)
{
    int idx = blockIdx.x*256 + threadIdx.x;     // 0 .. 81919
    if (idx >= BB*PLEN*CDIM) return;
    int b   = idx / (PLEN*CDIM);
    int rem = idx % (PLEN*CDIM);
    const float* base = g_pp + (long)b*NW*PLEN*CDIM + rem;
    float s = 0.f;
    #pragma unroll 8
    for (int w = 0; w < NW; w++) s += base[w*PLEN*CDIM];
    pout[idx] = s * (1.0f / NW);
}

// ============================================================================
extern "C" void kernel_launch(void* const* d_in, const int* in_sizes, int n_in,
                              void* d_out, int out_size)
{
    const float* x     = (const float*)d_in[0];  // (2048, 49, 128)
    const float* pr    = (const float*)d_in[1];  // (32, 20, 128)
    const float* mask  = (const float*)d_in[2];  // (64, 49, 49)
    const float* table = (const float*)d_in[3];  // (169, 4)
    const float* Wqkv  = (const float*)d_in[4];  // (128, 384)
    const float* bqkv  = (const float*)d_in[5];  // (384,)
    const float* Wproj = (const float*)d_in[6];  // (128, 128)
    const float* bproj = (const float*)d_in[7];  // (128,)

    float* out   = (float*)d_out;
    float* xout  = out;                                        // 2048*49*128
    float* attnw = out  + (long)B_TOT*NWIN*CDIM;               // 2048*4*20*49
    float* pout  = attnw + (long)B_TOT*HEADS*PLEN*NWIN;        // 32*20*128

    qkv_kernel <<<dim3(NROWS/64, 3), 256>>>(x, pr, Wqkv, bqkv);
    attn_kernel<<<B_TOT*HEADS, 256>>>(table, mask, attnw);
    proj_kernel<<<NROWS/64, 256>>>(Wproj, bproj, xout);
    pmean_kernel<<<(BB*PLEN*CDIM + 255)/256, 256>>>(pout);
}

// round 3
// speedup vs baseline: 1.9035x; 1.9035x over previous
#include <cuda_runtime.h>
#include <cuda_bf16.h>
#include <cstdint>
#include <math.h>

// ---------------- problem constants ----------------
#define B_TOT   2048
#define NW      64
#define BB      32
#define NWIN    49
#define PLEN    20
#define NTOK    69
#define CDIM    128
#define HEADS   4
#define DH      32
#define QK_SCALE 0.17677669529663687f
#define WROWS   100352            // 2048*49 window rows
#define PROWS   640               // 32*20 unique prompt rows
#define MROWS   100992            // WROWS + PROWS == 789*128
#define MT      789

// ---------------- scratch ----------------
__device__ __nv_bfloat16 g_a_hi[MROWS*CDIM];
__device__ __nv_bfloat16 g_a_lo[MROWS*CDIM];
__device__ __nv_bfloat16 g_wq_hi[384*CDIM];     // W_qkv^T [384][128]  (n-major, k contig)
__device__ __nv_bfloat16 g_wq_lo[384*CDIM];
__device__ __nv_bfloat16 g_wp_hi[CDIM*CDIM];    // W_proj^T [128][128]
__device__ __nv_bfloat16 g_wp_lo[CDIM*CDIM];
__device__ float g_qw[(long)B_TOT*HEADS*NWIN*DH];
__device__ float g_kw[(long)B_TOT*HEADS*NWIN*DH];
__device__ float g_vw[(long)B_TOT*HEADS*NWIN*DH];
__device__ float g_qp[BB*HEADS*PLEN*DH];
__device__ float g_kp[BB*HEADS*PLEN*DH];
__device__ float g_vp[BB*HEADS*PLEN*DH];
__device__ float g_aop[(long)B_TOT*PLEN*CDIM];  // per-window prompt attn outputs
__device__ __nv_bfloat16 g_pa_hi[MROWS*CDIM];   // proj input (attn output), split
__device__ __nv_bfloat16 g_pa_lo[MROWS*CDIM];

// ---------------- mma helper ----------------
__device__ __forceinline__ void mma16816(float* c, const uint32_t* a, const uint32_t* b) {
    asm volatile(
        "mma.sync.aligned.m16n8k16.row.col.f32.bf16.bf16.f32 "
        "{%0,%1,%2,%3}, {%4,%5,%6,%7}, {%8,%9}, {%0,%1,%2,%3};"
        : "+f"(c[0]), "+f"(c[1]), "+f"(c[2]), "+f"(c[3])
        : "r"(a[0]), "r"(a[1]), "r"(a[2]), "r"(a[3]), "r"(b[0]), "r"(b[1]));
}

// ============================================================================
// conv_a: build bf16 hi/lo A matrix (window rows then unique prompt rows)
// ============================================================================
__global__ void conv_a(const float* __restrict__ x, const float* __restrict__ spa)
{
    long i4 = (long)blockIdx.x * 256 + threadIdx.x;
    if (i4 >= (long)MROWS * CDIM / 4) return;
    long base = i4 * 4;
    const long wend = (long)WROWS * CDIM;
    const float* src = (base < wend) ? (x + base) : (spa + (base - wend));
    float4 v = *(const float4*)src;
    float f[4] = {v.x, v.y, v.z, v.w};
    union { __nv_bfloat16 b[4]; uint2 u; } ph, pl;
    #pragma unroll
    for (int i = 0; i < 4; i++) {
        ph.b[i] = __float2bfloat16(f[i]);
        pl.b[i] = __float2bfloat16(f[i] - __bfloat162float(ph.b[i]));
    }
    *(uint2*)(g_a_hi + base) = ph.u;
    *(uint2*)(g_a_lo + base) = pl.u;
}

// ============================================================================
// conv_w: transpose + split weights
// ============================================================================
__global__ void conv_w(const float* __restrict__ Wqkv, const float* __restrict__ Wproj)
{
    int idx = blockIdx.x * 256 + threadIdx.x;
    if (idx < 384 * 128) {
        int j = idx >> 7, k = idx & 127;
        float v = Wqkv[k * 384 + j];
        __nv_bfloat16 h = __float2bfloat16(v);
        g_wq_hi[idx] = h;
        g_wq_lo[idx] = __float2bfloat16(v - __bfloat162float(h));
    } else if (idx < 384 * 128 + 128 * 128) {
        int t = idx - 384 * 128;
        int n = t >> 7, k = t & 127;
        float v = Wproj[k * 128 + n];
        __nv_bfloat16 h = __float2bfloat16(v);
        g_wp_hi[t] = h;
        g_wp_lo[t] = __float2bfloat16(v - __bfloat162float(h));
    }
}

// ============================================================================
// gemm_mma: 128x128x128 bf16x3-split GEMM tile via mma.sync.m16n8k16.
// MODE 0: QKV (blockIdx.y selects q/k/v; scatter to [b,h,n,d] layouts)
// MODE 1: proj (out0 = x_out window rows, out1 = prompts_out)
// SRC  0: A = g_a_*;  SRC 1: A = g_pa_*
// ============================================================================
#define SKEW 40   // bf16 elements per smem row (32 data + 8 pad); 80B row, 16B-aligned

template<int MODE, int SRC>
__global__ void __launch_bounds__(256)
gemm_mma(const float* __restrict__ bias, float* __restrict__ out0, float* __restrict__ out1)
{
    __shared__ __nv_bfloat16 sAh[128][SKEW];
    __shared__ __nv_bfloat16 sAl[128][SKEW];
    __shared__ __nv_bfloat16 sBh[128][SKEW];
    __shared__ __nv_bfloat16 sBl[128][SKEW];

    const int tid  = threadIdx.x;
    const int w    = tid >> 5;          // 8 warps
    const int lane = tid & 31;
    const int gid  = lane >> 2;         // 0..7
    const int tg   = lane & 3;          // 0..3
    const long row0 = (long)blockIdx.x * 128;
    const int which = (MODE == 0) ? blockIdx.y : 0;

    const __nv_bfloat16* Ah = (SRC == 0 ? g_a_hi : g_pa_hi) + row0 * 128;
    const __nv_bfloat16* Al = (SRC == 0 ? g_a_lo : g_pa_lo) + row0 * 128;
    const __nv_bfloat16* Bh = (MODE == 0 ? g_wq_hi : g_wp_hi) + (long)which * 128 * 128;
    const __nv_bfloat16* Bl = (MODE == 0 ? g_wq_lo : g_wp_lo) + (long)which * 128 * 128;

    float acc[16][4];
    #pragma unroll
    for (int i = 0; i < 16; i++)
        #pragma unroll
        for (int j = 0; j < 4; j++) acc[i][j] = 0.f;

    const int arow = w * 16 + gid;      // A frag base row for this thread

    for (int k0 = 0; k0 < 128; k0 += 32) {
        // ---- fill smem: 128 rows x 32 k of each of 4 arrays (uint4 = 8 bf16) ----
        #pragma unroll
        for (int i = tid; i < 512; i += 256) {
            int r = i >> 2, c = i & 3;          // c: which 8-elem group
            const long go = (long)r * 128 + k0 + c * 8;
            *(uint4*)&sAh[r][c * 8] = *(const uint4*)(Ah + go);
            *(uint4*)&sAl[r][c * 8] = *(const uint4*)(Al + go);
            *(uint4*)&sBh[r][c * 8] = *(const uint4*)(Bh + go);
            *(uint4*)&sBl[r][c * 8] = *(const uint4*)(Bl + go);
        }
        __syncthreads();

        #pragma unroll
        for (int ks = 0; ks < 2; ks++) {
            const int kb = ks * 16;
            uint32_t ah[4], al[4];
            ah[0] = *(const uint32_t*)&sAh[arow    ][kb + tg * 2];
            ah[1] = *(const uint32_t*)&sAh[arow + 8][kb + tg * 2];
            ah[2] = *(const uint32_t*)&sAh[arow    ][kb + 8 + tg * 2];
            ah[3] = *(const uint32_t*)&sAh[arow + 8][kb + 8 + tg * 2];
            al[0] = *(const uint32_t*)&sAl[arow    ][kb + tg * 2];
            al[1] = *(const uint32_t*)&sAl[arow + 8][kb + tg * 2];
            al[2] = *(const uint32_t*)&sAl[arow    ][kb + 8 + tg * 2];
            al[3] = *(const uint32_t*)&sAl[arow + 8][kb + 8 + tg * 2];

            #pragma unroll
            for (int nf = 0; nf < 16; nf++) {
                const int brow = nf * 8 + gid;
                uint32_t bh[2], bl[2];
                bh[0] = *(const uint32_t*)&sBh[brow][kb + tg * 2];
                bh[1] = *(const uint32_t*)&sBh[brow][kb + 8 + tg * 2];
                bl[0] = *(const uint32_t*)&sBl[brow][kb + tg * 2];
                bl[1] = *(const uint32_t*)&sBl[brow][kb + 8 + tg * 2];
                mma16816(acc[nf], ah, bh);
                mma16816(acc[nf], ah, bl);
                mma16816(acc[nf], al, bh);
            }
        }
        __syncthreads();
    }

    // ---- epilogue ----
    const long r_lo = row0 + arow;
    const long r_hi = r_lo + 8;

    #pragma unroll
    for (int nf = 0; nf < 16; nf++) {
        const int c  = nf * 8 + tg * 2;
        const float bx = bias[(MODE == 0 ? which * 128 : 0) + c];
        const float by = bias[(MODE == 0 ? which * 128 : 0) + c + 1];
        if (MODE == 0) {
            float* dw; float* dp;
            if (which == 0)      { dw = g_qw; dp = g_qp; }
            else if (which == 1) { dw = g_kw; dp = g_kp; }
            else                 { dw = g_vw; dp = g_vp; }
            const int h = c >> 5, d = c & 31;
            #pragma unroll
            for (int half = 0; half < 2; half++) {
                const long r = half ? r_hi : r_lo;
                float vx = acc[nf][half * 2 + 0] + bx;
                float vy = acc[nf][half * 2 + 1] + by;
                float* dst;
                if (r < WROWS) {
                    int b_ = (int)(r / 49), n = (int)(r % 49);
                    dst = dw + (((long)b_ * HEADS + h) * NWIN + n) * DH + d;
                } else {
                    int pr = (int)(r - WROWS);
                    int b = pr / 20, p = pr % 20;
                    dst = dp + (((long)b * HEADS + h) * PLEN + p) * DH + d;
                }
                dst[0] = vx; dst[1] = vy;
            }
        } else {
            #pragma unroll
            for (int half = 0; half < 2; half++) {
                const long r = half ? r_hi : r_lo;
                float vx = acc[nf][half * 2 + 0] + bx;
                float vy = acc[nf][half * 2 + 1] + by;
                float* dst = (r < WROWS) ? (out0 + r * 128 + c)
                                         : (out1 + (r - WROWS) * 128 + c);
                dst[0] = vx; dst[1] = vy;
            }
        }
    }
}

// ============================================================================
// attn: per (b_, h). scores -> raw export -> scale+bias+mask -> softmax -> AV
// ============================================================================
__global__ void attn_kernel(const float* __restrict__ table,
                            const float* __restrict__ mask,
                            float* __restrict__ out_attnw)
{
    __shared__ float q_s[NTOK][DH+1];
    __shared__ float k_s[NTOK][DH+1];
    __shared__ float v_s[NTOK][DH+1];
    __shared__ float s_s[NTOK][NTOK+3];

    const int bh = blockIdx.x;
    const int b_ = bh >> 2;
    const int h  = bh & 3;
    const int b  = b_ >> 6;
    const int tid = threadIdx.x;

    const float* qw = g_qw + (long)bh * NWIN * DH;
    const float* kw = g_kw + (long)bh * NWIN * DH;
    const float* vw = g_vw + (long)bh * NWIN * DH;
    const float* qp = g_qp + ((long)b * HEADS + h) * PLEN * DH;
    const float* kp = g_kp + ((long)b * HEADS + h) * PLEN * DH;
    const float* vp = g_vp + ((long)b * HEADS + h) * PLEN * DH;

    for (int i = tid; i < NTOK * DH; i += 256) {
        int n = i >> 5, d = i & 31;
        if (n < PLEN) {
            q_s[n][d] = qp[n * DH + d];
            k_s[n][d] = kp[n * DH + d];
            v_s[n][d] = vp[n * DH + d];
        } else {
            int nn = n - PLEN;
            q_s[n][d] = qw[nn * DH + d];
            k_s[n][d] = kw[nn * DH + d];
            v_s[n][d] = vw[nn * DH + d];
        }
    }
    __syncthreads();

    const int w = b_ & (NW - 1);
    const float* mrow = mask + (long)w * NWIN * NWIN;

    for (int idx = tid; idx < NTOK * NTOK; idx += 256) {
        int n = idx / NTOK, m = idx % NTOK;
        float s = 0.f;
        #pragma unroll
        for (int d = 0; d < DH; d++) s = fmaf(q_s[n][d], k_s[m][d], s);
        if (n < PLEN && m >= PLEN)
            out_attnw[((long)bh * PLEN + n) * NWIN + (m - PLEN)] = s;
        s *= QK_SCALE;
        if (n >= PLEN && m >= PLEN) {
            int i = n - PLEN, j = m - PLEN;
            int dr = (i / 7) - (j / 7) + 6;
            int dc = (i % 7) - (j % 7) + 6;
            s += table[(dr * 13 + dc) * HEADS + h] + mrow[i * NWIN + j];
        }
        s_s[n][m] = s;
    }
    __syncthreads();

    const int warp = tid >> 5, lane = tid & 31;
    for (int n = warp; n < NTOK; n += 8) {
        float mx = -INFINITY;
        for (int m = lane; m < NTOK; m += 32) mx = fmaxf(mx, s_s[n][m]);
        #pragma unroll
        for (int o = 16; o > 0; o >>= 1) mx = fmaxf(mx, __shfl_xor_sync(0xffffffffu, mx, o));
        float sum = 0.f;
        for (int m = lane; m < NTOK; m += 32) {
            float e = __expf(s_s[n][m] - mx);
            s_s[n][m] = e;
            sum += e;
        }
        #pragma unroll
        for (int o = 16; o > 0; o >>= 1) sum += __shfl_xor_sync(0xffffffffu, sum, o);
        float inv = 1.0f / sum;
        for (int m = lane; m < NTOK; m += 32) s_s[n][m] *= inv;
    }
    __syncthreads();

    for (int idx = tid; idx < NTOK * DH; idx += 256) {
        int n = idx >> 5, d = idx & 31;
        float acc = 0.f;
        #pragma unroll 4
        for (int m = 0; m < NTOK; m++) acc = fmaf(s_s[n][m], v_s[m][d], acc);
        if (n < PLEN) {
            g_aop[((long)b_ * PLEN + n) * CDIM + h * DH + d] = acc;
        } else {
            long row = (long)b_ * NWIN + (n - PLEN);
            int col = h * DH + d;
            __nv_bfloat16 hi = __float2bfloat16(acc);
            g_pa_hi[row * CDIM + col] = hi;
            g_pa_lo[row * CDIM + col] = __float2bfloat16(acc - __bfloat162float(hi));
        }
    }
}

// ============================================================================
// pmean: prompt attn-output mean over windows -> proj-input rows WROWS..
// ============================================================================
__global__ void pmean_kernel()
{
    int idx = blockIdx.x * 256 + threadIdx.x;
    if (idx >= BB * PLEN * CDIM) return;
    int b = idx / (PLEN * CDIM);
    int rem = idx % (PLEN * CDIM);
    const float* base = g_aop + ((long)b * NW) * PLEN * CDIM + rem;
    float s = 0.f;
    #pragma unroll 8
    for (int w = 0; w < NW; w++) s += base[(long)w * PLEN * CDIM];
    s *= (1.0f / NW);
    long e = (long)WROWS * CDIM + idx;
    __nv_bfloat16 hi = __float2bfloat16(s);
    g_pa_hi[e] = hi;
    g_pa_lo[e] = __float2bfloat16(s - __bfloat162float(hi));
}

// ============================================================================
extern "C" void kernel_launch(void* const* d_in, const int* in_sizes, int n_in,
                              void* d_out, int out_size)
{
    const float* x     = (const float*)d_in[0];
    const float* pr    = (const float*)d_in[1];
    const float* mask  = (const float*)d_in[2];
    const float* table = (const float*)d_in[3];
    const float* Wqkv  = (const float*)d_in[4];
    const float* bqkv  = (const float*)d_in[5];
    const float* Wproj = (const float*)d_in[6];
    const float* bproj = (const float*)d_in[7];

    float* out   = (float*)d_out;
    float* xout  = out;
    float* attnw = out + (long)B_TOT * NWIN * CDIM;
    float* pout  = attnw + (long)B_TOT * HEADS * PLEN * NWIN;

    long nconv = (long)MROWS * CDIM / 4;
    conv_a<<<(int)((nconv + 255) / 256), 256>>>(x, pr);
    conv_w<<<(384*128 + 128*128 + 255) / 256, 256>>>(Wqkv, Wproj);
    gemm_mma<0,0><<<dim3(MT, 3), 256>>>(bqkv, nullptr, nullptr);
    attn_kernel<<<B_TOT * HEADS, 256>>>(table, mask, attnw);
    pmean_kernel<<<(BB * PLEN * CDIM + 255) / 256, 256>>>();
    gemm_mma<1,1><<<dim3(MT, 1), 256>>>(bproj, xout, pout);
}

// round 4
// speedup vs baseline: 2.5376x; 1.3331x over previous
#include <cuda_runtime.h>
#include <cuda_bf16.h>
#include <cstdint>
#include <math.h>

// ---------------- problem constants ----------------
#define B_TOT   2048
#define NW      64
#define BB      32
#define NWIN    49
#define PLEN    20
#define NTOK    69
#define CDIM    128
#define HEADS   4
#define DH      32
#define QK_SCALE 0.17677669529663687f
#define WROWS   100352
#define PROWS   640
#define MROWS   100992            // == 789*128
#define MT      789

// ---------------- scratch ----------------
__device__ __nv_bfloat16 g_a_hi[MROWS*CDIM];
__device__ __nv_bfloat16 g_a_lo[MROWS*CDIM];
__device__ __nv_bfloat16 g_wq_hi[384*CDIM];
__device__ __nv_bfloat16 g_wq_lo[384*CDIM];
__device__ __nv_bfloat16 g_wp_hi[CDIM*CDIM];
__device__ __nv_bfloat16 g_wp_lo[CDIM*CDIM];
// q/k/v as bf16 hi/lo, layout [bh][n][32] (window) and [b*4+h][p][32] (prompt)
#define WQKV ((long)B_TOT*HEADS*NWIN*DH)
#define PQKV (BB*HEADS*PLEN*DH)
__device__ __nv_bfloat16 g_qwh[WQKV]; __device__ __nv_bfloat16 g_qwl[WQKV];
__device__ __nv_bfloat16 g_kwh[WQKV]; __device__ __nv_bfloat16 g_kwl[WQKV];
__device__ __nv_bfloat16 g_vwh[WQKV]; __device__ __nv_bfloat16 g_vwl[WQKV];
__device__ __nv_bfloat16 g_qph[PQKV]; __device__ __nv_bfloat16 g_qpl[PQKV];
__device__ __nv_bfloat16 g_kph[PQKV]; __device__ __nv_bfloat16 g_kpl[PQKV];
__device__ __nv_bfloat16 g_vph[PQKV]; __device__ __nv_bfloat16 g_vpl[PQKV];
__device__ float g_aop[(long)B_TOT*PLEN*CDIM];
__device__ __nv_bfloat16 g_pa_hi[MROWS*CDIM];
__device__ __nv_bfloat16 g_pa_lo[MROWS*CDIM];

// ---------------- mma helper ----------------
__device__ __forceinline__ void mma16816(float* c, const uint32_t* a, const uint32_t* b) {
    asm volatile(
        "mma.sync.aligned.m16n8k16.row.col.f32.bf16.bf16.f32 "
        "{%0,%1,%2,%3}, {%4,%5,%6,%7}, {%8,%9}, {%0,%1,%2,%3};"
        : "+f"(c[0]), "+f"(c[1]), "+f"(c[2]), "+f"(c[3])
        : "r"(a[0]), "r"(a[1]), "r"(a[2]), "r"(a[3]), "r"(b[0]), "r"(b[1]));
}

// fast exp on the FMA pipe (no MUFU). x clamped to >= -80.
__device__ __forceinline__ float fexp(float x) {
    x = fmaxf(x, -80.f);
    float t  = fmaf(x, 1.4426950408889634f, 12582912.0f);
    float fi = t - 12582912.0f;
    float f  = fmaf(x, 1.4426950408889634f, -fi);
    float p  = 1.3333558146e-3f;
    p = fmaf(p, f, 9.6181291076e-3f);
    p = fmaf(p, f, 5.5504108664e-2f);
    p = fmaf(p, f, 2.4022650696e-1f);
    p = fmaf(p, f, 6.9314718056e-1f);
    p = fmaf(p, f, 1.0f);
    int ii = (int)fi;
    float s = __int_as_float((ii + 127) << 23);
    return p * s;
}

__device__ __forceinline__ uint32_t pack_bf2(float x, float y) {
    __nv_bfloat162 v; v.x = __float2bfloat16(x); v.y = __float2bfloat16(y);
    return *(uint32_t*)&v;
}

// ============================================================================
// conv_a / conv_w (unchanged)
// ============================================================================
__global__ void conv_a(const float* __restrict__ x, const float* __restrict__ spa)
{
    long i4 = (long)blockIdx.x * 256 + threadIdx.x;
    if (i4 >= (long)MROWS * CDIM / 4) return;
    long base = i4 * 4;
    const long wend = (long)WROWS * CDIM;
    const float* src = (base < wend) ? (x + base) : (spa + (base - wend));
    float4 v = *(const float4*)src;
    float f[4] = {v.x, v.y, v.z, v.w};
    union { __nv_bfloat16 b[4]; uint2 u; } ph, pl;
    #pragma unroll
    for (int i = 0; i < 4; i++) {
        ph.b[i] = __float2bfloat16(f[i]);
        pl.b[i] = __float2bfloat16(f[i] - __bfloat162float(ph.b[i]));
    }
    *(uint2*)(g_a_hi + base) = ph.u;
    *(uint2*)(g_a_lo + base) = pl.u;
}

__global__ void conv_w(const float* __restrict__ Wqkv, const float* __restrict__ Wproj)
{
    int idx = blockIdx.x * 256 + threadIdx.x;
    if (idx < 384 * 128) {
        int j = idx >> 7, k = idx & 127;
        float v = Wqkv[k * 384 + j];
        __nv_bfloat16 h = __float2bfloat16(v);
        g_wq_hi[idx] = h;
        g_wq_lo[idx] = __float2bfloat16(v - __bfloat162float(h));
    } else if (idx < 384 * 128 + 128 * 128) {
        int t = idx - 384 * 128;
        int n = t >> 7, k = t & 127;
        float v = Wproj[k * 128 + n];
        __nv_bfloat16 h = __float2bfloat16(v);
        g_wp_hi[t] = h;
        g_wp_lo[t] = __float2bfloat16(v - __bfloat162float(h));
    }
}

// ============================================================================
// gemm_mma: 128x128x128 bf16x3-split GEMM tile.
// MODE 0: QKV  -> writes q/k/v as bf16 hi/lo pairs
// MODE 1: proj -> out0 = x_out, out1 = prompts_out
// ============================================================================
#define SKEW 40

template<int MODE, int SRC>
__global__ void __launch_bounds__(256)
gemm_mma(const float* __restrict__ bias, float* __restrict__ out0, float* __restrict__ out1)
{
    __shared__ __nv_bfloat16 sAh[128][SKEW];
    __shared__ __nv_bfloat16 sAl[128][SKEW];
    __shared__ __nv_bfloat16 sBh[128][SKEW];
    __shared__ __nv_bfloat16 sBl[128][SKEW];

    const int tid  = threadIdx.x;
    const int w    = tid >> 5;
    const int lane = tid & 31;
    const int gid  = lane >> 2;
    const int tg   = lane & 3;
    const long row0 = (long)blockIdx.x * 128;
    const int which = (MODE == 0) ? blockIdx.y : 0;

    const __nv_bfloat16* Ah = (SRC == 0 ? g_a_hi : g_pa_hi) + row0 * 128;
    const __nv_bfloat16* Al = (SRC == 0 ? g_a_lo : g_pa_lo) + row0 * 128;
    const __nv_bfloat16* Bh = (MODE == 0 ? g_wq_hi : g_wp_hi) + (long)which * 128 * 128;
    const __nv_bfloat16* Bl = (MODE == 0 ? g_wq_lo : g_wp_lo) + (long)which * 128 * 128;

    float acc[16][4];
    #pragma unroll
    for (int i = 0; i < 16; i++)
        #pragma unroll
        for (int j = 0; j < 4; j++) acc[i][j] = 0.f;

    const int arow = w * 16 + gid;

    for (int k0 = 0; k0 < 128; k0 += 32) {
        #pragma unroll
        for (int i = tid; i < 512; i += 256) {
            int r = i >> 2, c = i & 3;
            const long go = (long)r * 128 + k0 + c * 8;
            *(uint4*)&sAh[r][c * 8] = *(const uint4*)(Ah + go);
            *(uint4*)&sAl[r][c * 8] = *(const uint4*)(Al + go);
            *(uint4*)&sBh[r][c * 8] = *(const uint4*)(Bh + go);
            *(uint4*)&sBl[r][c * 8] = *(const uint4*)(Bl + go);
        }
        __syncthreads();

        #pragma unroll
        for (int ks = 0; ks < 2; ks++) {
            const int kb = ks * 16;
            uint32_t ah[4], al[4];
            ah[0] = *(const uint32_t*)&sAh[arow    ][kb + tg * 2];
            ah[1] = *(const uint32_t*)&sAh[arow + 8][kb + tg * 2];
            ah[2] = *(const uint32_t*)&sAh[arow    ][kb + 8 + tg * 2];
            ah[3] = *(const uint32_t*)&sAh[arow + 8][kb + 8 + tg * 2];
            al[0] = *(const uint32_t*)&sAl[arow    ][kb + tg * 2];
            al[1] = *(const uint32_t*)&sAl[arow + 8][kb + tg * 2];
            al[2] = *(const uint32_t*)&sAl[arow    ][kb + 8 + tg * 2];
            al[3] = *(const uint32_t*)&sAl[arow + 8][kb + 8 + tg * 2];

            #pragma unroll
            for (int nf = 0; nf < 16; nf++) {
                const int brow = nf * 8 + gid;
                uint32_t bh[2], bl[2];
                bh[0] = *(const uint32_t*)&sBh[brow][kb + tg * 2];
                bh[1] = *(const uint32_t*)&sBh[brow][kb + 8 + tg * 2];
                bl[0] = *(const uint32_t*)&sBl[brow][kb + tg * 2];
                bl[1] = *(const uint32_t*)&sBl[brow][kb + 8 + tg * 2];
                mma16816(acc[nf], ah, bh);
                mma16816(acc[nf], ah, bl);
                mma16816(acc[nf], al, bh);
            }
        }
        __syncthreads();
    }

    const long r_lo = row0 + arow;

    #pragma unroll
    for (int nf = 0; nf < 16; nf++) {
        const int c  = nf * 8 + tg * 2;
        const float bx = bias[(MODE == 0 ? which * 128 : 0) + c];
        const float by = bias[(MODE == 0 ? which * 128 : 0) + c + 1];
        #pragma unroll
        for (int half = 0; half < 2; half++) {
            const long r = r_lo + half * 8;
            float vx = acc[nf][half * 2 + 0] + bx;
            float vy = acc[nf][half * 2 + 1] + by;
            if (MODE == 0) {
                const int h = c >> 5, d = c & 31;
                __nv_bfloat16 hx = __float2bfloat16(vx);
                __nv_bfloat16 hy = __float2bfloat16(vy);
                uint32_t uh = pack_bf2(vx, vy);   // hi pair
                __nv_bfloat162 lo2;
                lo2.x = __float2bfloat16(vx - __bfloat162float(hx));
                lo2.y = __float2bfloat16(vy - __bfloat162float(hy));
                uint32_t ul = *(uint32_t*)&lo2;
                __nv_bfloat16 *dh, *dl;
                long off;
                if (r < WROWS) {
                    int b_ = (int)(r / 49), n = (int)(r % 49);
                    off = (((long)b_ * HEADS + h) * NWIN + n) * DH + d;
                    if (which == 0)      { dh = g_qwh; dl = g_qwl; }
                    else if (which == 1) { dh = g_kwh; dl = g_kwl; }
                    else                 { dh = g_vwh; dl = g_vwl; }
                } else {
                    int pr = (int)(r - WROWS);
                    int b = pr / 20, p = pr % 20;
                    off = (((long)b * HEADS + h) * PLEN + p) * DH + d;
                    if (which == 0)      { dh = g_qph; dl = g_qpl; }
                    else if (which == 1) { dh = g_kph; dl = g_kpl; }
                    else                 { dh = g_vph; dl = g_vpl; }
                }
                *(uint32_t*)(dh + off) = uh;
                *(uint32_t*)(dl + off) = ul;
            } else {
                float* dst = (r < WROWS) ? (out0 + r * 128 + c)
                                         : (out1 + (r - WROWS) * 128 + c);
                dst[0] = vx; dst[1] = vy;
            }
        }
    }
}

// ============================================================================
// attn_mma: one CTA per (b_, h), 128 threads, tensor-core attention.
// ============================================================================
#define QS 40
#define SS 76
#define PS 88
#define VS 88
#define OFF_QH  0
#define OFF_QL  (80*QS*2)
#define OFF_KH  (2*80*QS*2)
#define OFF_KL  (OFF_KH + 72*QS*2)
#define OFF_PBH 0
#define OFF_PBL (80*PS*2)
#define REGION_P (2*80*PS*2)
#define OFF_S   REGION_P
#define OFF_VTH (REGION_P + 80*SS*4)
#define OFF_VTL (OFF_VTH + 32*VS*2)
#define SMEM_ATTN (OFF_VTL + 32*VS*2)

__global__ void __launch_bounds__(128)
attn_mma(const float* __restrict__ table, const float* __restrict__ mask,
         float* __restrict__ out_attnw)
{
    extern __shared__ char sm[];
    const int bh  = blockIdx.x;
    const int b_  = bh >> 2;
    const int h   = bh & 3;
    const int b   = b_ >> 6;
    const int tid = threadIdx.x;
    const int w   = tid >> 5;
    const int lane = tid & 31;
    const int gid = lane >> 2;
    const int tg  = lane & 3;

    __nv_bfloat16* qh = (__nv_bfloat16*)(sm + OFF_QH);
    __nv_bfloat16* ql = (__nv_bfloat16*)(sm + OFF_QL);
    __nv_bfloat16* kh = (__nv_bfloat16*)(sm + OFF_KH);
    __nv_bfloat16* kl = (__nv_bfloat16*)(sm + OFF_KL);
    float*         ss = (float*)(sm + OFF_S);
    __nv_bfloat16* vth = (__nv_bfloat16*)(sm + OFF_VTH);
    __nv_bfloat16* vtl = (__nv_bfloat16*)(sm + OFF_VTL);

    // ---- load q/k hi+lo (rows 0..68, 4 x uint4 chunks per row) ----
    for (int i = tid; i < 2 * 276; i += 128) {
        int t = (i >= 276);
        int j = t ? (i - 276) : i;
        int r = j >> 2, c = j & 3;
        long off;
        const __nv_bfloat16 *srch, *srcl;
        if (r < PLEN) {
            off = (((long)(b * HEADS + h)) * PLEN + r) * DH;
            srch = (t ? g_kph : g_qph) + off;
            srcl = (t ? g_kpl : g_qpl) + off;
        } else {
            off = ((long)bh * NWIN + (r - PLEN)) * DH;
            srch = (t ? g_kwh : g_qwh) + off;
            srcl = (t ? g_kwl : g_qwl) + off;
        }
        __nv_bfloat16* dh = (t ? kh : qh) + r * QS + c * 8;
        __nv_bfloat16* dl = (t ? kl : ql) + r * QS + c * 8;
        *(uint4*)dh = ((const uint4*)srch)[c];
        *(uint4*)dl = ((const uint4*)srcl)[c];
    }
    // ---- load v and transpose into vT [d][m] ----
    for (int i = tid; i < 69 * 16; i += 128) {
        int r = i >> 4, dp = (i & 15) * 2;
        long off;
        const __nv_bfloat16 *sh, *sl;
        if (r < PLEN) {
            off = (((long)(b * HEADS + h)) * PLEN + r) * DH + dp;
            sh = g_vph + off; sl = g_vpl + off;
        } else {
            off = ((long)bh * NWIN + (r - PLEN)) * DH + dp;
            sh = g_vwh + off; sl = g_vwl + off;
        }
        __nv_bfloat162 vh2 = *(const __nv_bfloat162*)sh;
        __nv_bfloat162 vl2 = *(const __nv_bfloat162*)sl;
        vth[dp * VS + r] = vh2.x; vth[(dp + 1) * VS + r] = vh2.y;
        vtl[dp * VS + r] = vl2.x; vtl[(dp + 1) * VS + r] = vl2.y;
    }
    // zero vT pad cols 69..79
    for (int i = tid; i < 32 * 11; i += 128) {
        int d = i / 11, c = 69 + (i % 11);
        ((uint16_t*)vth)[d * VS + c] = 0;
        ((uint16_t*)vtl)[d * VS + c] = 0;
    }
    __syncthreads();

    // ---- scores: S = Q . K^T  (raw, fp32 accum, bf16x3) ----
    for (int mt = w; mt < 5; mt += 4) {
        float acc[9][4];
        #pragma unroll
        for (int i = 0; i < 9; i++)
            #pragma unroll
            for (int j = 0; j < 4; j++) acc[i][j] = 0.f;
        const int arow = mt * 16 + gid;
        #pragma unroll
        for (int ks = 0; ks < 2; ks++) {
            const int kb = ks * 16;
            uint32_t ah[4], al[4];
            ah[0] = *(uint32_t*)&qh[arow * QS + kb + tg * 2];
            ah[1] = *(uint32_t*)&qh[(arow + 8) * QS + kb + tg * 2];
            ah[2] = *(uint32_t*)&qh[arow * QS + kb + 8 + tg * 2];
            ah[3] = *(uint32_t*)&qh[(arow + 8) * QS + kb + 8 + tg * 2];
            al[0] = *(uint32_t*)&ql[arow * QS + kb + tg * 2];
            al[1] = *(uint32_t*)&ql[(arow + 8) * QS + kb + tg * 2];
            al[2] = *(uint32_t*)&ql[arow * QS + kb + 8 + tg * 2];
            al[3] = *(uint32_t*)&ql[(arow + 8) * QS + kb + 8 + tg * 2];
            #pragma unroll
            for (int nt = 0; nt < 9; nt++) {
                const int brow = nt * 8 + gid;
                uint32_t bhf[2], blf[2];
                bhf[0] = *(uint32_t*)&kh[brow * QS + kb + tg * 2];
                bhf[1] = *(uint32_t*)&kh[brow * QS + kb + 8 + tg * 2];
                blf[0] = *(uint32_t*)&kl[brow * QS + kb + tg * 2];
                blf[1] = *(uint32_t*)&kl[brow * QS + kb + 8 + tg * 2];
                mma16816(acc[nt], ah, bhf);
                mma16816(acc[nt], ah, blf);
                mma16816(acc[nt], al, bhf);
            }
        }
        #pragma unroll
        for (int nt = 0; nt < 9; nt++) {
            const int col = nt * 8 + tg * 2;
            *(float2*)&ss[arow * SS + col]       = make_float2(acc[nt][0], acc[nt][1]);
            *(float2*)&ss[(arow + 8) * SS + col] = make_float2(acc[nt][2], acc[nt][3]);
        }
    }
    __syncthreads();

    // ---- export raw + scale + bias + mask + softmax -> probs bf16 hi/lo ----
    __nv_bfloat16* pbh = (__nv_bfloat16*)(sm + OFF_PBH);
    __nv_bfloat16* pbl = (__nv_bfloat16*)(sm + OFF_PBL);
    const float* mrow = mask + (long)(b_ & 63) * NWIN * NWIN;

    for (int n = w; n < 69; n += 4) {
        const int ii = n - PLEN;
        const int idiv = ii / 7, imod = ii - idiv * 7;
        float sv[3];
        #pragma unroll
        for (int sl2 = 0; sl2 < 3; sl2++) {
            int m = lane + sl2 * 32;
            float val = -1e30f;
            if (m < 69) {
                float raw = ss[n * SS + m];
                val = raw * QK_SCALE;
                if (n < PLEN) {
                    if (m >= PLEN)
                        out_attnw[((long)bh * PLEN + n) * NWIN + (m - PLEN)] = raw;
                } else if (m >= PLEN) {
                    int j = m - PLEN;
                    int jdiv = j / 7, jmod = j - jdiv * 7;
                    int dr = idiv - jdiv + 6;
                    int dc = imod - jmod + 6;
                    val += table[(dr * 13 + dc) * HEADS + h] + mrow[ii * NWIN + j];
                }
            }
            sv[sl2] = val;
        }
        float mx = fmaxf(fmaxf(sv[0], sv[1]), sv[2]);
        #pragma unroll
        for (int o = 16; o > 0; o >>= 1) mx = fmaxf(mx, __shfl_xor_sync(0xffffffffu, mx, o));
        float e[3]; float sum = 0.f;
        #pragma unroll
        for (int sl2 = 0; sl2 < 3; sl2++) {
            int m = lane + sl2 * 32;
            e[sl2] = (m < 69) ? fexp(sv[sl2] - mx) : 0.f;
            sum += e[sl2];
        }
        #pragma unroll
        for (int o = 16; o > 0; o >>= 1) sum += __shfl_xor_sync(0xffffffffu, sum, o);
        float inv = 1.0f / sum;
        #pragma unroll
        for (int sl2 = 0; sl2 < 3; sl2++) {
            int m = lane + sl2 * 32;
            if (m < 80) {
                float p = e[sl2] * inv;
                __nv_bfloat16 ph = __float2bfloat16(p);
                pbh[n * PS + m] = ph;
                pbl[n * PS + m] = __float2bfloat16(p - __bfloat162float(ph));
            }
        }
    }
    __syncthreads();

    // ---- AV: out = P . V  (P hi/lo x V hi/lo, 3-product) ----
    for (int mt = w; mt < 5; mt += 4) {
        float acc[4][4];
        #pragma unroll
        for (int i = 0; i < 4; i++)
            #pragma unroll
            for (int j = 0; j < 4; j++) acc[i][j] = 0.f;
        const int arow = mt * 16 + gid;
        #pragma unroll
        for (int kt = 0; kt < 5; kt++) {
            const int kb = kt * 16;
            uint32_t ph4[4], pl4[4];
            ph4[0] = *(uint32_t*)&pbh[arow * PS + kb + tg * 2];
            ph4[1] = *(uint32_t*)&pbh[(arow + 8) * PS + kb + tg * 2];
            ph4[2] = *(uint32_t*)&pbh[arow * PS + kb + 8 + tg * 2];
            ph4[3] = *(uint32_t*)&pbh[(arow + 8) * PS + kb + 8 + tg * 2];
            pl4[0] = *(uint32_t*)&pbl[arow * PS + kb + tg * 2];
            pl4[1] = *(uint32_t*)&pbl[(arow + 8) * PS + kb + tg * 2];
            pl4[2] = *(uint32_t*)&pbl[arow * PS + kb + 8 + tg * 2];
            pl4[3] = *(uint32_t*)&pbl[(arow + 8) * PS + kb + 8 + tg * 2];
            #pragma unroll
            for (int nt = 0; nt < 4; nt++) {
                const int brow = nt * 8 + gid;
                uint32_t bh2[2], bl2[2];
                bh2[0] = *(uint32_t*)&vth[brow * VS + kb + tg * 2];
                bh2[1] = *(uint32_t*)&vth[brow * VS + kb + 8 + tg * 2];
                bl2[0] = *(uint32_t*)&vtl[brow * VS + kb + tg * 2];
                bl2[1] = *(uint32_t*)&vtl[brow * VS + kb + 8 + tg * 2];
                mma16816(acc[nt], ph4, bh2);
                mma16816(acc[nt], ph4, bl2);
                mma16816(acc[nt], pl4, bh2);
            }
        }
        #pragma unroll
        for (int nt = 0; nt < 4; nt++) {
            const int d = nt * 8 + tg * 2;
            #pragma unroll
            for (int half = 0; half < 2; half++) {
                const int n = arow + half * 8;
                if (n >= 69) continue;
                float vx = acc[nt][half * 2 + 0];
                float vy = acc[nt][half * 2 + 1];
                if (n < PLEN) {
                    float* dst = g_aop + ((long)b_ * PLEN + n) * CDIM + h * DH + d;
                    dst[0] = vx; dst[1] = vy;
                } else {
                    long row = (long)b_ * NWIN + (n - PLEN);
                    int col = h * DH + d;
                    __nv_bfloat16 hx = __float2bfloat16(vx);
                    __nv_bfloat16 hy = __float2bfloat16(vy);
                    *(uint32_t*)&g_pa_hi[row * CDIM + col] = pack_bf2(vx, vy);
                    __nv_bfloat162 lo2;
                    lo2.x = __float2bfloat16(vx - __bfloat162float(hx));
                    lo2.y = __float2bfloat16(vy - __bfloat162float(hy));
                    *(uint32_t*)&g_pa_lo[row * CDIM + col] = *(uint32_t*)&lo2;
                }
            }
        }
    }
}

// ============================================================================
// pmean: prompt attn-output mean over windows -> proj-input rows WROWS..
// ============================================================================
__global__ void pmean_kernel()
{
    int idx = blockIdx.x * 256 + threadIdx.x;
    if (idx >= BB * PLEN * CDIM) return;
    int b = idx / (PLEN * CDIM);
    int rem = idx % (PLEN * CDIM);
    const float* base = g_aop + ((long)b * NW) * PLEN * CDIM + rem;
    float s = 0.f;
    #pragma unroll 8
    for (int w = 0; w < NW; w++) s += base[(long)w * PLEN * CDIM];
    s *= (1.0f / NW);
    long e = (long)WROWS * CDIM + idx;
    __nv_bfloat16 hi = __float2bfloat16(s);
    g_pa_hi[e] = hi;
    g_pa_lo[e] = __float2bfloat16(s - __bfloat162float(hi));
}

// ============================================================================
extern "C" void kernel_launch(void* const* d_in, const int* in_sizes, int n_in,
                              void* d_out, int out_size)
{
    const float* x     = (const float*)d_in[0];
    const float* pr    = (const float*)d_in[1];
    const float* mask  = (const float*)d_in[2];
    const float* table = (const float*)d_in[3];
    const float* Wqkv  = (const float*)d_in[4];
    const float* bqkv  = (const float*)d_in[5];
    const float* Wproj = (const float*)d_in[6];
    const float* bproj = (const float*)d_in[7];

    float* out   = (float*)d_out;
    float* xout  = out;
    float* attnw = out + (long)B_TOT * NWIN * CDIM;
    float* pout  = attnw + (long)B_TOT * HEADS * PLEN * NWIN;

    static int configured = 0;
    if (!configured) {
        cudaFuncSetAttribute(attn_mma, cudaFuncAttributeMaxDynamicSharedMemorySize, SMEM_ATTN);
        configured = 1;
    }

    long nconv = (long)MROWS * CDIM / 4;
    conv_a<<<(int)((nconv + 255) / 256), 256>>>(x, pr);
    conv_w<<<(384*128 + 128*128 + 255) / 256, 256>>>(Wqkv, Wproj);
    gemm_mma<0,0><<<dim3(MT, 3), 256>>>(bqkv, nullptr, nullptr);
    attn_mma<<<B_TOT * HEADS, 128, SMEM_ATTN>>>(table, mask, attnw);
    pmean_kernel<<<(BB * PLEN * CDIM + 255) / 256, 256>>>();
    gemm_mma<1,1><<<dim3(MT, 1), 256>>>(bproj, xout, pout);
}

// round 5
// speedup vs baseline: 3.8026x; 1.4985x over previous
#include <cuda_runtime.h>
#include <cuda_bf16.h>
#include <cstdint>
#include <math.h>

// ---------------- problem constants ----------------
#define B_TOT   2048
#define NW      64
#define BB      32
#define NWIN    49
#define PLEN    20
#define NTOK    69
#define CDIM    128
#define HEADS   4
#define DH      32
#define QK_SCALE 0.17677669529663687f
#define WROWS   100352
#define PROWS   640
#define MROWS   100992            // == 789*128
#define MT      789

// ---------------- scratch ----------------
__device__ __nv_bfloat16 g_a_hi[MROWS*CDIM];
__device__ __nv_bfloat16 g_a_lo[MROWS*CDIM];
__device__ __nv_bfloat16 g_wq_hi[384*CDIM];
__device__ __nv_bfloat16 g_wq_lo[384*CDIM];
__device__ __nv_bfloat16 g_wp_hi[CDIM*CDIM];
__device__ __nv_bfloat16 g_wp_lo[CDIM*CDIM];
#define WQKV ((long)B_TOT*HEADS*NWIN*DH)
#define PQKV (BB*HEADS*PLEN*DH)
__device__ __nv_bfloat16 g_qwh[WQKV]; __device__ __nv_bfloat16 g_qwl[WQKV];
__device__ __nv_bfloat16 g_kwh[WQKV]; __device__ __nv_bfloat16 g_kwl[WQKV];
__device__ __nv_bfloat16 g_vwh[WQKV]; __device__ __nv_bfloat16 g_vwl[WQKV];
__device__ __nv_bfloat16 g_qph[PQKV]; __device__ __nv_bfloat16 g_qpl[PQKV];
__device__ __nv_bfloat16 g_kph[PQKV]; __device__ __nv_bfloat16 g_kpl[PQKV];
__device__ __nv_bfloat16 g_vph[PQKV]; __device__ __nv_bfloat16 g_vpl[PQKV];
__device__ float g_aop[(long)B_TOT*PLEN*CDIM];
__device__ __nv_bfloat16 g_pa_hi[MROWS*CDIM];
__device__ __nv_bfloat16 g_pa_lo[MROWS*CDIM];

// ---------------- mma helper ----------------
__device__ __forceinline__ void mma16816(float* c, const uint32_t* a, const uint32_t* b) {
    asm volatile(
        "mma.sync.aligned.m16n8k16.row.col.f32.bf16.bf16.f32 "
        "{%0,%1,%2,%3}, {%4,%5,%6,%7}, {%8,%9}, {%0,%1,%2,%3};"
        : "+f"(c[0]), "+f"(c[1]), "+f"(c[2]), "+f"(c[3])
        : "r"(a[0]), "r"(a[1]), "r"(a[2]), "r"(a[3]), "r"(b[0]), "r"(b[1]));
}

// fast exp on the FMA pipe (no MUFU). x clamped to >= -80.
__device__ __forceinline__ float fexp(float x) {
    x = fmaxf(x, -80.f);
    float t  = fmaf(x, 1.4426950408889634f, 12582912.0f);
    float fi = t - 12582912.0f;
    float f  = fmaf(x, 1.4426950408889634f, -fi);
    float p  = 1.3333558146e-3f;
    p = fmaf(p, f, 9.6181291076e-3f);
    p = fmaf(p, f, 5.5504108664e-2f);
    p = fmaf(p, f, 2.4022650696e-1f);
    p = fmaf(p, f, 6.9314718056e-1f);
    p = fmaf(p, f, 1.0f);
    int ii = (int)fi;
    float s = __int_as_float((ii + 127) << 23);
    return p * s;
}

__device__ __forceinline__ uint32_t pack_bf2(float x, float y) {
    __nv_bfloat162 v; v.x = __float2bfloat16(x); v.y = __float2bfloat16(y);
    return *(uint32_t*)&v;
}
__device__ __forceinline__ uint32_t pack_bf2_lo(float x, float y, uint32_t hi) {
    __nv_bfloat162 hv = *(__nv_bfloat162*)&hi;
    __nv_bfloat162 v;
    v.x = __float2bfloat16(x - __bfloat162float(hv.x));
    v.y = __float2bfloat16(y - __bfloat162float(hv.y));
    return *(uint32_t*)&v;
}

// ============================================================================
// conv_a / conv_w
// ============================================================================
__global__ void conv_a(const float* __restrict__ x, const float* __restrict__ spa)
{
    long i4 = (long)blockIdx.x * 256 + threadIdx.x;
    if (i4 >= (long)MROWS * CDIM / 4) return;
    long base = i4 * 4;
    const long wend = (long)WROWS * CDIM;
    const float* src = (base < wend) ? (x + base) : (spa + (base - wend));
    float4 v = *(const float4*)src;
    float f[4] = {v.x, v.y, v.z, v.w};
    union { __nv_bfloat16 b[4]; uint2 u; } ph, pl;
    #pragma unroll
    for (int i = 0; i < 4; i++) {
        ph.b[i] = __float2bfloat16(f[i]);
        pl.b[i] = __float2bfloat16(f[i] - __bfloat162float(ph.b[i]));
    }
    *(uint2*)(g_a_hi + base) = ph.u;
    *(uint2*)(g_a_lo + base) = pl.u;
}

__global__ void conv_w(const float* __restrict__ Wqkv, const float* __restrict__ Wproj)
{
    int idx = blockIdx.x * 256 + threadIdx.x;
    if (idx < 384 * 128) {
        int j = idx >> 7, k = idx & 127;
        float v = Wqkv[k * 384 + j];
        __nv_bfloat16 h = __float2bfloat16(v);
        g_wq_hi[idx] = h;
        g_wq_lo[idx] = __float2bfloat16(v - __bfloat162float(h));
    } else if (idx < 384 * 128 + 128 * 128) {
        int t = idx - 384 * 128;
        int n = t >> 7, k = t & 127;
        float v = Wproj[k * 128 + n];
        __nv_bfloat16 h = __float2bfloat16(v);
        g_wp_hi[t] = h;
        g_wp_lo[t] = __float2bfloat16(v - __bfloat162float(h));
    }
}

// ============================================================================
// gemm_mma (unchanged from round 4)
// ============================================================================
#define SKEW 40

template<int MODE, int SRC>
__global__ void __launch_bounds__(256)
gemm_mma(const float* __restrict__ bias, float* __restrict__ out0, float* __restrict__ out1)
{
    __shared__ __nv_bfloat16 sAh[128][SKEW];
    __shared__ __nv_bfloat16 sAl[128][SKEW];
    __shared__ __nv_bfloat16 sBh[128][SKEW];
    __shared__ __nv_bfloat16 sBl[128][SKEW];

    const int tid  = threadIdx.x;
    const int w    = tid >> 5;
    const int lane = tid & 31;
    const int gid  = lane >> 2;
    const int tg   = lane & 3;
    const long row0 = (long)blockIdx.x * 128;
    const int which = (MODE == 0) ? blockIdx.y : 0;

    const __nv_bfloat16* Ah = (SRC == 0 ? g_a_hi : g_pa_hi) + row0 * 128;
    const __nv_bfloat16* Al = (SRC == 0 ? g_a_lo : g_pa_lo) + row0 * 128;
    const __nv_bfloat16* Bh = (MODE == 0 ? g_wq_hi : g_wp_hi) + (long)which * 128 * 128;
    const __nv_bfloat16* Bl = (MODE == 0 ? g_wq_lo : g_wp_lo) + (long)which * 128 * 128;

    float acc[16][4];
    #pragma unroll
    for (int i = 0; i < 16; i++)
        #pragma unroll
        for (int j = 0; j < 4; j++) acc[i][j] = 0.f;

    const int arow = w * 16 + gid;

    for (int k0 = 0; k0 < 128; k0 += 32) {
        #pragma unroll
        for (int i = tid; i < 512; i += 256) {
            int r = i >> 2, c = i & 3;
            const long go = (long)r * 128 + k0 + c * 8;
            *(uint4*)&sAh[r][c * 8] = *(const uint4*)(Ah + go);
            *(uint4*)&sAl[r][c * 8] = *(const uint4*)(Al + go);
            *(uint4*)&sBh[r][c * 8] = *(const uint4*)(Bh + go);
            *(uint4*)&sBl[r][c * 8] = *(const uint4*)(Bl + go);
        }
        __syncthreads();

        #pragma unroll
        for (int ks = 0; ks < 2; ks++) {
            const int kb = ks * 16;
            uint32_t ah[4], al[4];
            ah[0] = *(const uint32_t*)&sAh[arow    ][kb + tg * 2];
            ah[1] = *(const uint32_t*)&sAh[arow + 8][kb + tg * 2];
            ah[2] = *(const uint32_t*)&sAh[arow    ][kb + 8 + tg * 2];
            ah[3] = *(const uint32_t*)&sAh[arow + 8][kb + 8 + tg * 2];
            al[0] = *(const uint32_t*)&sAl[arow    ][kb + tg * 2];
            al[1] = *(const uint32_t*)&sAl[arow + 8][kb + tg * 2];
            al[2] = *(const uint32_t*)&sAl[arow    ][kb + 8 + tg * 2];
            al[3] = *(const uint32_t*)&sAl[arow + 8][kb + 8 + tg * 2];

            #pragma unroll
            for (int nf = 0; nf < 16; nf++) {
                const int brow = nf * 8 + gid;
                uint32_t bh[2], bl[2];
                bh[0] = *(const uint32_t*)&sBh[brow][kb + tg * 2];
                bh[1] = *(const uint32_t*)&sBh[brow][kb + 8 + tg * 2];
                bl[0] = *(const uint32_t*)&sBl[brow][kb + tg * 2];
                bl[1] = *(const uint32_t*)&sBl[brow][kb + 8 + tg * 2];
                mma16816(acc[nf], ah, bh);
                mma16816(acc[nf], ah, bl);
                mma16816(acc[nf], al, bh);
            }
        }
        __syncthreads();
    }

    const long r_lo = row0 + arow;

    #pragma unroll
    for (int nf = 0; nf < 16; nf++) {
        const int c  = nf * 8 + tg * 2;
        const float bx = bias[(MODE == 0 ? which * 128 : 0) + c];
        const float by = bias[(MODE == 0 ? which * 128 : 0) + c + 1];
        #pragma unroll
        for (int half = 0; half < 2; half++) {
            const long r = r_lo + half * 8;
            float vx = acc[nf][half * 2 + 0] + bx;
            float vy = acc[nf][half * 2 + 1] + by;
            if (MODE == 0) {
                const int h = c >> 5, d = c & 31;
                uint32_t uh = pack_bf2(vx, vy);
                uint32_t ul = pack_bf2_lo(vx, vy, uh);
                __nv_bfloat16 *dh, *dl;
                long off;
                if (r < WROWS) {
                    int b_ = (int)(r / 49), n = (int)(r % 49);
                    off = (((long)b_ * HEADS + h) * NWIN + n) * DH + d;
                    if (which == 0)      { dh = g_qwh; dl = g_qwl; }
                    else if (which == 1) { dh = g_kwh; dl = g_kwl; }
                    else                 { dh = g_vwh; dl = g_vwl; }
                } else {
                    int pr = (int)(r - WROWS);
                    int b = pr / 20, p = pr % 20;
                    off = (((long)b * HEADS + h) * PLEN + p) * DH + d;
                    if (which == 0)      { dh = g_qph; dl = g_qpl; }
                    else if (which == 1) { dh = g_kph; dl = g_kpl; }
                    else                 { dh = g_vph; dl = g_vpl; }
                }
                *(uint32_t*)(dh + off) = uh;
                *(uint32_t*)(dl + off) = ul;
            } else {
                float* dst = (r < WROWS) ? (out0 + r * 128 + c)
                                         : (out1 + (r - WROWS) * 128 + c);
                dst[0] = vx; dst[1] = vy;
            }
        }
    }
}

// ============================================================================
// attn_mma v2: register-resident scores/probs. 160 threads = 5 warps,
// one 16-row m-tile per warp; one sync total.
// ============================================================================
#define QS 40
#define VS 88

__global__ void __launch_bounds__(160, 4)
attn_mma(const float* __restrict__ table, const float* __restrict__ mask,
         float* __restrict__ out_attnw)
{
    __shared__ __nv_bfloat16 qh[80][QS], ql[80][QS];
    __shared__ __nv_bfloat16 kh[72][QS], kl[72][QS];
    __shared__ __nv_bfloat16 vth[32][VS], vtl[32][VS];

    const int bh  = blockIdx.x;
    const int b_  = bh >> 2;
    const int h   = bh & 3;
    const int b   = b_ >> 6;
    const int tid = threadIdx.x;
    const int w   = tid >> 5;
    const int lane = tid & 31;
    const int gid = lane >> 2;
    const int tg  = lane & 3;

    // ---- load q/k hi+lo ----
    for (int i = tid; i < 2 * 276; i += 160) {
        int t = (i >= 276);
        int j = t ? (i - 276) : i;
        int r = j >> 2, c = j & 3;
        long off;
        const __nv_bfloat16 *srch, *srcl;
        if (r < PLEN) {
            off = (((long)(b * HEADS + h)) * PLEN + r) * DH;
            srch = (t ? g_kph : g_qph) + off;
            srcl = (t ? g_kpl : g_qpl) + off;
        } else {
            off = ((long)bh * NWIN + (r - PLEN)) * DH;
            srch = (t ? g_kwh : g_qwh) + off;
            srcl = (t ? g_kwl : g_qwl) + off;
        }
        if (t) {
            *(uint4*)&kh[r][c * 8] = ((const uint4*)srch)[c];
            *(uint4*)&kl[r][c * 8] = ((const uint4*)srcl)[c];
        } else {
            *(uint4*)&qh[r][c * 8] = ((const uint4*)srch)[c];
            *(uint4*)&ql[r][c * 8] = ((const uint4*)srcl)[c];
        }
    }
    // ---- load v, transpose to [d][m] ----
    for (int i = tid; i < 69 * 16; i += 160) {
        int r = i >> 4, dp = (i & 15) * 2;
        long off;
        const __nv_bfloat16 *sh, *sl;
        if (r < PLEN) {
            off = (((long)(b * HEADS + h)) * PLEN + r) * DH + dp;
            sh = g_vph + off; sl = g_vpl + off;
        } else {
            off = ((long)bh * NWIN + (r - PLEN)) * DH + dp;
            sh = g_vwh + off; sl = g_vwl + off;
        }
        __nv_bfloat162 vh2 = *(const __nv_bfloat162*)sh;
        __nv_bfloat162 vl2 = *(const __nv_bfloat162*)sl;
        vth[dp][r] = vh2.x; vth[dp + 1][r] = vh2.y;
        vtl[dp][r] = vl2.x; vtl[dp + 1][r] = vl2.y;
    }
    // zero vT pad cols 69..79
    for (int i = tid; i < 32 * 11; i += 160) {
        int d = i / 11, c = 69 + (i % 11);
        vth[d][c] = __float2bfloat16(0.f);
        vtl[d][c] = __float2bfloat16(0.f);
    }
    __syncthreads();

    const int row0 = w * 16 + gid;   // query rows owned by this thread
    const int row1 = row0 + 8;

    // ---- scores: register-resident, bf16x3 ----
    float acc[9][4];
    #pragma unroll
    for (int i = 0; i < 9; i++)
        #pragma unroll
        for (int j = 0; j < 4; j++) acc[i][j] = 0.f;

    #pragma unroll
    for (int ks = 0; ks < 2; ks++) {
        const int kb = ks * 16;
        uint32_t ah[4], al[4];
        ah[0] = *(uint32_t*)&qh[row0][kb + tg * 2];
        ah[1] = *(uint32_t*)&qh[row1][kb + tg * 2];
        ah[2] = *(uint32_t*)&qh[row0][kb + 8 + tg * 2];
        ah[3] = *(uint32_t*)&qh[row1][kb + 8 + tg * 2];
        al[0] = *(uint32_t*)&ql[row0][kb + tg * 2];
        al[1] = *(uint32_t*)&ql[row1][kb + tg * 2];
        al[2] = *(uint32_t*)&ql[row0][kb + 8 + tg * 2];
        al[3] = *(uint32_t*)&ql[row1][kb + 8 + tg * 2];
        #pragma unroll
        for (int nt = 0; nt < 9; nt++) {
            const int brow = nt * 8 + gid;
            uint32_t bhf[2], blf[2];
            bhf[0] = *(uint32_t*)&kh[brow][kb + tg * 2];
            bhf[1] = *(uint32_t*)&kh[brow][kb + 8 + tg * 2];
            blf[0] = *(uint32_t*)&kl[brow][kb + tg * 2];
            blf[1] = *(uint32_t*)&kl[brow][kb + 8 + tg * 2];
            mma16816(acc[nt], ah, bhf);
            mma16816(acc[nt], ah, blf);
            mma16816(acc[nt], al, bhf);
        }
    }

    // ---- per-element: raw export, scale, bias, mask ----
    const float* mrow = mask + (long)(b_ & 63) * NWIN * NWIN;
    const int i0 = row0 - PLEN, i1 = row1 - PLEN;
    const int i0d = i0 / 7, i0m = i0 - i0d * 7;
    const int i1d = i1 / 7, i1m = i1 - i1d * 7;

    #pragma unroll
    for (int nt = 0; nt < 9; nt++) {
        #pragma unroll
        for (int e = 0; e < 4; e++) {
            const int r  = (e & 2) ? row1 : row0;
            const int c  = nt * 8 + tg * 2 + (e & 1);
            float raw = acc[nt][e];
            float v;
            if (c >= NTOK || r >= NTOK) {
                v = -1e30f;
            } else if (r < PLEN) {
                if (c >= PLEN)
                    out_attnw[((long)bh * PLEN + r) * NWIN + (c - PLEN)] = raw;
                v = raw * QK_SCALE;
            } else {
                v = raw * QK_SCALE;
                if (c >= PLEN) {
                    const int j = c - PLEN;
                    const int jd = j / 7, jm = j - jd * 7;
                    const int dr = ((e & 2) ? i1d : i0d) - jd + 6;
                    const int dc = ((e & 2) ? i1m : i0m) - jm + 6;
                    v += table[(dr * 13 + dc) * HEADS + h] + mrow[((e & 2) ? i1 : i0) * NWIN + j];
                }
            }
            acc[nt][e] = v;
        }
    }

    // ---- softmax across the quad (rows row0, row1 independently) ----
    float mx0 = -1e30f, mx1 = -1e30f;
    #pragma unroll
    for (int nt = 0; nt < 9; nt++) {
        mx0 = fmaxf(mx0, fmaxf(acc[nt][0], acc[nt][1]));
        mx1 = fmaxf(mx1, fmaxf(acc[nt][2], acc[nt][3]));
    }
    #pragma unroll
    for (int o = 1; o <= 2; o <<= 1) {
        mx0 = fmaxf(mx0, __shfl_xor_sync(0xffffffffu, mx0, o));
        mx1 = fmaxf(mx1, __shfl_xor_sync(0xffffffffu, mx1, o));
    }
    float sum0 = 0.f, sum1 = 0.f;
    #pragma unroll
    for (int nt = 0; nt < 9; nt++) {
        acc[nt][0] = fexp(acc[nt][0] - mx0);
        acc[nt][1] = fexp(acc[nt][1] - mx0);
        acc[nt][2] = fexp(acc[nt][2] - mx1);
        acc[nt][3] = fexp(acc[nt][3] - mx1);
        sum0 += acc[nt][0] + acc[nt][1];
        sum1 += acc[nt][2] + acc[nt][3];
    }
    #pragma unroll
    for (int o = 1; o <= 2; o <<= 1) {
        sum0 += __shfl_xor_sync(0xffffffffu, sum0, o);
        sum1 += __shfl_xor_sync(0xffffffffu, sum1, o);
    }
    const float inv0 = 1.0f / sum0;
    const float inv1 = 1.0f / sum1;

    // ---- pack probs to bf16 hi/lo A-fragments ----
    uint32_t pah[5][4], pal[5][4];
    #pragma unroll
    for (int nt = 0; nt < 9; nt++) {
        float p0 = acc[nt][0] * inv0;
        float p1 = acc[nt][1] * inv0;
        float p2 = acc[nt][2] * inv1;
        float p3 = acc[nt][3] * inv1;
        uint32_t h01 = pack_bf2(p0, p1);
        uint32_t l01 = pack_bf2_lo(p0, p1, h01);
        uint32_t h23 = pack_bf2(p2, p3);
        uint32_t l23 = pack_bf2_lo(p2, p3, h23);
        const int kt = nt >> 1;
        const int s  = (nt & 1) * 2;
        pah[kt][s + 0] = h01;  pah[kt][s + 1] = h23;
        pal[kt][s + 0] = l01;  pal[kt][s + 1] = l23;
    }
    pah[4][2] = pah[4][3] = 0;
    pal[4][2] = pal[4][3] = 0;

    // ---- AV: out = P . V ----
    float oacc[4][4];
    #pragma unroll
    for (int i = 0; i < 4; i++)
        #pragma unroll
        for (int j = 0; j < 4; j++) oacc[i][j] = 0.f;

    #pragma unroll
    for (int kt = 0; kt < 5; kt++) {
        const int kb = kt * 16;
        #pragma unroll
        for (int nt = 0; nt < 4; nt++) {
            const int brow = nt * 8 + gid;
            uint32_t bh2[2], bl2[2];
            bh2[0] = *(uint32_t*)&vth[brow][kb + tg * 2];
            bh2[1] = *(uint32_t*)&vth[brow][kb + 8 + tg * 2];
            bl2[0] = *(uint32_t*)&vtl[brow][kb + tg * 2];
            bl2[1] = *(uint32_t*)&vtl[brow][kb + 8 + tg * 2];
            mma16816(oacc[nt], pah[kt], bh2);
            mma16816(oacc[nt], pah[kt], bl2);
            mma16816(oacc[nt], pal[kt], bh2);
        }
    }

    // ---- store ----
    #pragma unroll
    for (int nt = 0; nt < 4; nt++) {
        const int d = nt * 8 + tg * 2;
        #pragma unroll
        for (int half = 0; half < 2; half++) {
            const int n = (half ? row1 : row0);
            if (n >= NTOK) continue;
            float vx = oacc[nt][half * 2 + 0];
            float vy = oacc[nt][half * 2 + 1];
            if (n < PLEN) {
                float* dst = g_aop + ((long)b_ * PLEN + n) * CDIM + h * DH + d;
                dst[0] = vx; dst[1] = vy;
            } else {
                long row = (long)b_ * NWIN + (n - PLEN);
                int col = h * DH + d;
                uint32_t uh = pack_bf2(vx, vy);
                *(uint32_t*)&g_pa_hi[row * CDIM + col] = uh;
                *(uint32_t*)&g_pa_lo[row * CDIM + col] = pack_bf2_lo(vx, vy, uh);
            }
        }
    }
}

// ============================================================================
// pmean
// ============================================================================
__global__ void pmean_kernel()
{
    int idx = blockIdx.x * 256 + threadIdx.x;
    if (idx >= BB * PLEN * CDIM) return;
    int b = idx / (PLEN * CDIM);
    int rem = idx % (PLEN * CDIM);
    const float* base = g_aop + ((long)b * NW) * PLEN * CDIM + rem;
    float s = 0.f;
    #pragma unroll 8
    for (int w = 0; w < NW; w++) s += base[(long)w * PLEN * CDIM];
    s *= (1.0f / NW);
    long e = (long)WROWS * CDIM + idx;
    __nv_bfloat16 hi = __float2bfloat16(s);
    g_pa_hi[e] = hi;
    g_pa_lo[e] = __float2bfloat16(s - __bfloat162float(hi));
}

// ============================================================================
extern "C" void kernel_launch(void* const* d_in, const int* in_sizes, int n_in,
                              void* d_out, int out_size)
{
    const float* x     = (const float*)d_in[0];
    const float* pr    = (const float*)d_in[1];
    const float* mask  = (const float*)d_in[2];
    const float* table = (const float*)d_in[3];
    const float* Wqkv  = (const float*)d_in[4];
    const float* bqkv  = (const float*)d_in[5];
    const float* Wproj = (const float*)d_in[6];
    const float* bproj = (const float*)d_in[7];

    float* out   = (float*)d_out;
    float* xout  = out;
    float* attnw = out + (long)B_TOT * NWIN * CDIM;
    float* pout  = attnw + (long)B_TOT * HEADS * PLEN * NWIN;

    long nconv = (long)MROWS * CDIM / 4;
    conv_a<<<(int)((nconv + 255) / 256), 256>>>(x, pr);
    conv_w<<<(384*128 + 128*128 + 255) / 256, 256>>>(Wqkv, Wproj);
    gemm_mma<0,0><<<dim3(MT, 3), 256>>>(bqkv, nullptr, nullptr);
    attn_mma<<<B_TOT * HEADS, 160>>>(table, mask, attnw);
    pmean_kernel<<<(BB * PLEN * CDIM + 255) / 256, 256>>>();
    gemm_mma<1,1><<<dim3(MT, 1), 256>>>(bproj, xout, pout);
}